// round 2
// baseline (speedup 1.0000x reference)
#include <cuda_runtime.h>

#define Bn 4
#define Cn 256
#define Hn 224
#define H0 112
#define H1 56

// Scratch (static __device__ arrays per allocation rules)
__device__ float g_d0[Bn*Cn*H0*H0];   // level-0 decompose, 112x112
__device__ float g_d1[Bn*Cn*H1*H1];   // level-1 decompose, 56x56
__device__ float g_s1[Bn*Cn*H1*H1];   // dw3x3(d1, Wsum1)
__device__ float g_t0[Bn*Cn*H0*H0];   // up(s1)+dw3x3(d0, Wsum0)

// K1: x -> d0 (112^2) and d1 (56^2). Each thread: one d1 pixel = 4x4 of x.
// Filter index q = c/64; sign pattern: row sign if q&1 (c bit6), col sign if q&2 (c bit7).
__global__ void k1_decompose(const float* __restrict__ x) {
    int bc = blockIdx.x;
    int c  = bc & (Cn - 1);
    float sR = (c & 64)  ? -1.f : 1.f;
    float sC = (c & 128) ? -1.f : 1.f;
    int i = blockIdx.y * blockDim.y + threadIdx.y;  // d1 row
    int j = threadIdx.x;                            // d1 col
    const float* xp = x + ((size_t)bc * Hn + 4 * i) * Hn + 4 * j;
    float4 r0 = *(const float4*)(xp);
    float4 r1 = *(const float4*)(xp + Hn);
    float4 r2 = *(const float4*)(xp + 2 * Hn);
    float4 r3 = *(const float4*)(xp + 3 * Hn);
    float d00 = 0.25f * (r0.x + sC * r0.y + sR * (r1.x + sC * r1.y));
    float d01 = 0.25f * (r0.z + sC * r0.w + sR * (r1.z + sC * r1.w));
    float d10 = 0.25f * (r2.x + sC * r2.y + sR * (r3.x + sC * r3.y));
    float d11 = 0.25f * (r2.z + sC * r2.w + sR * (r3.z + sC * r3.w));
    float* d0p = g_d0 + ((size_t)bc * H0 + 2 * i) * H0 + 2 * j;
    *(float2*)(d0p)      = make_float2(d00, d01);
    *(float2*)(d0p + H0) = make_float2(d10, d11);
    g_d1[((size_t)bc * H1 + i) * H1 + j] =
        0.25f * (d00 + sC * d01 + sR * (d10 + sC * d11));
}

// K2: s1 = dw3x3(d1, w_ll + w_lh1 + w_hl1 + w_hh1), zero-pad 1, 56x56.
__global__ void k2_s1(const float* __restrict__ wll, const float* __restrict__ wlh,
                      const float* __restrict__ whl, const float* __restrict__ whh) {
    __shared__ float w[9];
    int bc = blockIdx.x;
    int c  = bc & (Cn - 1);
    int t = threadIdx.y * blockDim.x + threadIdx.x;
    if (t < 9) {
        int o = c * 9 + t;
        w[t] = wll[o] + wlh[o] + whl[o] + whh[o];
    }
    __syncthreads();
    int u = blockIdx.y * blockDim.y + threadIdx.y;
    int v = threadIdx.x;
    const float* p = g_d1 + (size_t)bc * H1 * H1;
    float acc = 0.f;
    #pragma unroll
    for (int dy = -1; dy <= 1; dy++) {
        int yy = u + dy;
        if (yy < 0 || yy >= H1) continue;
        #pragma unroll
        for (int dx = -1; dx <= 1; dx++) {
            int xx = v + dx;
            if (xx < 0 || xx >= H1) continue;
            acc += w[(dy + 1) * 3 + (dx + 1)] * p[yy * H1 + xx];
        }
    }
    g_s1[(size_t)bc * H1 * H1 + u * H1 + v] = acc;
}

// K3: t0 = up(s1)*R_q + dw3x3(d0, w_lh0 + w_hl0 + w_hh0), 112x112.
__global__ void k3_t0(const float* __restrict__ wlh, const float* __restrict__ whl,
                      const float* __restrict__ whh) {
    __shared__ float w[9];
    int bc = blockIdx.x;
    int c  = bc & (Cn - 1);
    int t = threadIdx.y * blockDim.x + threadIdx.x;
    if (t < 9) {
        int o = c * 9 + t;
        w[t] = wlh[o] + whl[o] + whh[o];
    }
    __syncthreads();
    int u = blockIdx.y * blockDim.y + threadIdx.y;
    int v = threadIdx.x;
    const float* p = g_d0 + (size_t)bc * H0 * H0;
    float acc = 0.f;
    #pragma unroll
    for (int dy = -1; dy <= 1; dy++) {
        int yy = u + dy;
        if (yy < 0 || yy >= H0) continue;
        #pragma unroll
        for (int dx = -1; dx <= 1; dx++) {
            int xx = v + dx;
            if (xx < 0 || xx >= H0) continue;
            acc += w[(dy + 1) * 3 + (dx + 1)] * p[yy * H0 + xx];
        }
    }
    float su = ((u & 1) && (c & 64))  ? -1.f : 1.f;
    float sv = ((v & 1) && (c & 128)) ? -1.f : 1.f;
    float s1v = g_s1[(size_t)bc * H1 * H1 + (u >> 1) * H1 + (v >> 1)];
    g_t0[(size_t)bc * H0 * H0 + u * H0 + v] = acc + 0.5f * su * sv * s1v;
}

// K4: out = (dw3x3(x, base_w) + base_b)*base_scale + wavelet_scale * up(t0)*R_q.
// block (224,4), each block covers 16 rows via 4 iterations.
__global__ void k4_out(const float* __restrict__ x, const float* __restrict__ bw,
                       const float* __restrict__ bb, const float* __restrict__ bs,
                       const float* __restrict__ ws, float* __restrict__ out) {
    __shared__ float w[9];
    __shared__ float sc[3];
    int bc = blockIdx.x;
    int c  = bc & (Cn - 1);
    int t = threadIdx.y * blockDim.x + threadIdx.x;
    if (t < 9)       w[t]  = bw[c * 9 + t];
    else if (t == 9) sc[0] = bb[c];
    else if (t == 10) sc[1] = bs[c];
    else if (t == 11) sc[2] = ws[c];
    __syncthreads();
    const float* xp = x + (size_t)bc * Hn * Hn;
    const float* tp = g_t0 + (size_t)bc * H0 * H0;
    float* op = out + (size_t)bc * Hn * Hn;
    int v = threadIdx.x;
    float svb = ((v & 1) && (c & 128)) ? -1.f : 1.f;
    #pragma unroll
    for (int it = 0; it < 4; it++) {
        int y = blockIdx.y * 16 + it * 4 + threadIdx.y;
        float acc = 0.f;
        #pragma unroll
        for (int dy = -1; dy <= 1; dy++) {
            int yy = y + dy;
            if (yy < 0 || yy >= Hn) continue;
            #pragma unroll
            for (int dx = -1; dx <= 1; dx++) {
                int xx = v + dx;
                if (xx < 0 || xx >= Hn) continue;
                acc += w[(dy + 1) * 3 + (dx + 1)] * xp[yy * Hn + xx];
            }
        }
        float su = ((y & 1) && (c & 64)) ? -1.f : 1.f;
        float wt = 0.5f * su * svb * tp[(y >> 1) * H0 + (v >> 1)];
        op[y * Hn + v] = (acc + sc[0]) * sc[1] + sc[2] * wt;
    }
}

extern "C" void kernel_launch(void* const* d_in, const int* in_sizes, int n_in,
                              void* d_out, int out_size) {
    const float* x          = (const float*)d_in[0];
    const float* base_w     = (const float*)d_in[1];
    const float* base_b     = (const float*)d_in[2];
    const float* base_scale = (const float*)d_in[3];
    const float* wav_scale  = (const float*)d_in[4];
    const float* w_ll       = (const float*)d_in[5];
    const float* w_lh0      = (const float*)d_in[6];
    const float* w_hl0      = (const float*)d_in[7];
    const float* w_hh0      = (const float*)d_in[8];
    const float* w_lh1      = (const float*)d_in[9];
    const float* w_hl1      = (const float*)d_in[10];
    const float* w_hh1      = (const float*)d_in[11];
    float* out = (float*)d_out;

    k1_decompose<<<dim3(Bn * Cn, 14), dim3(56, 4)>>>(x);
    k2_s1<<<dim3(Bn * Cn, 7), dim3(56, 8)>>>(w_ll, w_lh1, w_hl1, w_hh1);
    k3_t0<<<dim3(Bn * Cn, 28), dim3(112, 4)>>>(w_lh0, w_hl0, w_hh0);
    k4_out<<<dim3(Bn * Cn, 14), dim3(224, 4)>>>(x, base_w, base_b, base_scale,
                                                wav_scale, out);
}

// round 3
// speedup vs baseline: 2.2363x; 2.2363x over previous
#include <cuda_runtime.h>

#define Bn 4
#define Cn 256
#define Hn 224
#define H0 112
#define H1 56

// Scratch (static __device__ arrays per allocation rules)
__device__ float g_d0[Bn*Cn*H0*H0];   // level-0 decompose, 112x112
__device__ float g_d1[Bn*Cn*H1*H1];   // level-1 decompose, 56x56
__device__ float g_s1[Bn*Cn*H1*H1];   // dw3x3(d1, Wsum1)
__device__ float g_t0[Bn*Cn*H0*H0];   // up(s1)+dw3x3(d0, Wsum0)

// K1: x -> d0 (112^2) and d1 (56^2). Each thread: one d1 pixel = 4x4 of x.
// Filter index q = c/64; signs: row sign if c&64, col sign if c&128.
__global__ void k1_decompose(const float* __restrict__ x) {
    int bc = blockIdx.x;
    int c  = bc & (Cn - 1);
    float sR = (c & 64)  ? -1.f : 1.f;
    float sC = (c & 128) ? -1.f : 1.f;
    int i = blockIdx.y * blockDim.y + threadIdx.y;  // d1 row
    int j = threadIdx.x;                            // d1 col
    const float* xp = x + ((size_t)bc * Hn + 4 * i) * Hn + 4 * j;
    float4 r0 = *(const float4*)(xp);
    float4 r1 = *(const float4*)(xp + Hn);
    float4 r2 = *(const float4*)(xp + 2 * Hn);
    float4 r3 = *(const float4*)(xp + 3 * Hn);
    float d00 = 0.25f * (r0.x + sC * r0.y + sR * (r1.x + sC * r1.y));
    float d01 = 0.25f * (r0.z + sC * r0.w + sR * (r1.z + sC * r1.w));
    float d10 = 0.25f * (r2.x + sC * r2.y + sR * (r3.x + sC * r3.y));
    float d11 = 0.25f * (r2.z + sC * r2.w + sR * (r3.z + sC * r3.w));
    float* d0p = g_d0 + ((size_t)bc * H0 + 2 * i) * H0 + 2 * j;
    *(float2*)(d0p)      = make_float2(d00, d01);
    *(float2*)(d0p + H0) = make_float2(d10, d11);
    g_d1[((size_t)bc * H1 + i) * H1 + j] =
        0.25f * (d00 + sC * d01 + sR * (d10 + sC * d11));
}

// K2: s1 = dw3x3(d1, w_ll + w_lh1 + w_hl1 + w_hh1), zero-pad 1, 56x56.
__global__ void k2_s1(const float* __restrict__ wll, const float* __restrict__ wlh,
                      const float* __restrict__ whl, const float* __restrict__ whh) {
    __shared__ float w[9];
    int bc = blockIdx.x;
    int c  = bc & (Cn - 1);
    int t = threadIdx.y * blockDim.x + threadIdx.x;
    if (t < 9) {
        int o = c * 9 + t;
        w[t] = wll[o] + wlh[o] + whl[o] + whh[o];
    }
    __syncthreads();
    int u = blockIdx.y * blockDim.y + threadIdx.y;
    int v = threadIdx.x;
    const float* p = g_d1 + (size_t)bc * H1 * H1;
    float acc = 0.f;
    #pragma unroll
    for (int dy = -1; dy <= 1; dy++) {
        int yy = u + dy;
        if (yy < 0 || yy >= H1) continue;
        #pragma unroll
        for (int dx = -1; dx <= 1; dx++) {
            int xx = v + dx;
            if (xx < 0 || xx >= H1) continue;
            acc += w[(dy + 1) * 3 + (dx + 1)] * p[yy * H1 + xx];
        }
    }
    g_s1[(size_t)bc * H1 * H1 + u * H1 + v] = acc;
}

// K3: t0 = up(s1)*R_q + dw3x3(d0, Wsum0), 112x112. Smem-tiled, float4 I/O.
// Block (28,8)=224 thr, 16 rows per block, grid (1024, 7).
__global__ void k3_t0(const float* __restrict__ wlh, const float* __restrict__ whl,
                      const float* __restrict__ whh) {
    __shared__ float w[9];
    __shared__ float sm[18][116];   // cols: idx 0 = col -1, idx 1+x = col x, idx 113 = col 112
    int bc = blockIdx.x;
    int c  = bc & (Cn - 1);
    int tid = threadIdx.y * 28 + threadIdx.x;
    if (tid < 9) {
        int o = c * 9 + tid;
        w[tid] = wlh[o] + whl[o] + whh[o];
    }
    if (tid < 18) { sm[tid][0] = 0.f; sm[tid][113] = 0.f; }
    const float* p = g_d0 + (size_t)bc * H0 * H0;
    int ybase = blockIdx.y * 16;
    // load 18 rows x 28 float4 = 504 vec loads, 224 threads -> 3 passes
    #pragma unroll
    for (int l = tid; l < 18 * 28; l += 224) {
        int r = l / 28, q = l % 28;
        int y = ybase - 1 + r;
        float4 v4 = make_float4(0.f, 0.f, 0.f, 0.f);
        if (y >= 0 && y < H0) v4 = *(const float4*)(p + y * H0 + 4 * q);
        sm[r][1 + 4 * q]     = v4.x;
        sm[r][1 + 4 * q + 1] = v4.y;
        sm[r][1 + 4 * q + 2] = v4.z;
        sm[r][1 + 4 * q + 3] = v4.w;
    }
    __syncthreads();
    const float* sp = g_s1 + (size_t)bc * H1 * H1;
    float* tp = g_t0 + (size_t)bc * H0 * H0;
    int x0 = 4 * threadIdx.x;
    float svb = (c & 128) ? -1.f : 1.f;   // sign on odd cols
    #pragma unroll
    for (int it = 0; it < 2; it++) {
        int rl = threadIdx.y + 8 * it;    // 0..15
        int y  = ybase + rl;
        int r  = rl + 1;
        float a0 = 0.f, a1 = 0.f, a2 = 0.f, a3 = 0.f;
        #pragma unroll
        for (int dy = 0; dy < 3; dy++) {
            const float* row = &sm[r - 1 + dy][x0];
            float c0 = row[0], c1 = row[1], c2 = row[2],
                  c3 = row[3], c4 = row[4], c5 = row[5];
            float w0 = w[dy * 3], w1 = w[dy * 3 + 1], w2 = w[dy * 3 + 2];
            a0 += w0 * c0 + w1 * c1 + w2 * c2;
            a1 += w0 * c1 + w1 * c2 + w2 * c3;
            a2 += w0 * c2 + w1 * c3 + w2 * c4;
            a3 += w0 * c3 + w1 * c4 + w2 * c5;
        }
        float su = ((y & 1) && (c & 64)) ? -1.f : 1.f;
        float2 tv = *(const float2*)(sp + (y >> 1) * H1 + (x0 >> 1));
        float we = 0.5f * su, wo = 0.5f * su * svb;
        float4 o4;
        o4.x = a0 + we * tv.x;
        o4.y = a1 + wo * tv.x;
        o4.z = a2 + we * tv.y;
        o4.w = a3 + wo * tv.y;
        *(float4*)(tp + y * H0 + x0) = o4;
    }
}

// K4: out = (dw3x3(x, base_w) + base_b)*base_scale + ws * up(t0)*R_q.
// Smem-tiled, float4 I/O. Block (56,8)=448 thr, 16 rows per block, grid (1024, 14).
__global__ void k4_out(const float* __restrict__ x, const float* __restrict__ bw,
                       const float* __restrict__ bb, const float* __restrict__ bs,
                       const float* __restrict__ ws, float* __restrict__ out) {
    __shared__ float w[9];
    __shared__ float sc[3];
    __shared__ float sm[18][228];   // idx 0 = col -1, idx 1+x = col x, idx 225 = col 224
    int bc = blockIdx.x;
    int c  = bc & (Cn - 1);
    int tid = threadIdx.y * 56 + threadIdx.x;
    if (tid < 9)        w[tid] = bw[c * 9 + tid];
    else if (tid == 9)  sc[0] = bb[c];
    else if (tid == 10) sc[1] = bs[c];
    else if (tid == 11) sc[2] = ws[c];
    if (tid < 18) { sm[tid][0] = 0.f; sm[tid][225] = 0.f; }
    const float* xp = x + (size_t)bc * Hn * Hn;
    int ybase = blockIdx.y * 16;
    // load 18 rows x 56 float4 = 1008 vec loads, 448 threads -> 3 passes
    #pragma unroll
    for (int l = tid; l < 18 * 56; l += 448) {
        int r = l / 56, q = l % 56;
        int y = ybase - 1 + r;
        float4 v4 = make_float4(0.f, 0.f, 0.f, 0.f);
        if (y >= 0 && y < Hn) v4 = *(const float4*)(xp + y * Hn + 4 * q);
        sm[r][1 + 4 * q]     = v4.x;
        sm[r][1 + 4 * q + 1] = v4.y;
        sm[r][1 + 4 * q + 2] = v4.z;
        sm[r][1 + 4 * q + 3] = v4.w;
    }
    __syncthreads();
    const float* tp = g_t0 + (size_t)bc * H0 * H0;
    float* op = out + (size_t)bc * Hn * Hn;
    int x0 = 4 * threadIdx.x;
    float svb = (c & 128) ? -1.f : 1.f;
    float bias = sc[0], bscale = sc[1], wsc = sc[2];
    #pragma unroll
    for (int it = 0; it < 2; it++) {
        int rl = threadIdx.y + 8 * it;
        int y  = ybase + rl;
        int r  = rl + 1;
        float a0 = 0.f, a1 = 0.f, a2 = 0.f, a3 = 0.f;
        #pragma unroll
        for (int dy = 0; dy < 3; dy++) {
            const float* row = &sm[r - 1 + dy][x0];
            float c0 = row[0], c1 = row[1], c2 = row[2],
                  c3 = row[3], c4 = row[4], c5 = row[5];
            float w0 = w[dy * 3], w1 = w[dy * 3 + 1], w2 = w[dy * 3 + 2];
            a0 += w0 * c0 + w1 * c1 + w2 * c2;
            a1 += w0 * c1 + w1 * c2 + w2 * c3;
            a2 += w0 * c2 + w1 * c3 + w2 * c4;
            a3 += w0 * c3 + w1 * c4 + w2 * c5;
        }
        float su = ((y & 1) && (c & 64)) ? -1.f : 1.f;
        float2 tv = *(const float2*)(tp + (y >> 1) * H0 + (x0 >> 1));
        float we = wsc * 0.5f * su, wo = we * svb;
        float4 o4;
        o4.x = (a0 + bias) * bscale + we * tv.x;
        o4.y = (a1 + bias) * bscale + wo * tv.x;
        o4.z = (a2 + bias) * bscale + we * tv.y;
        o4.w = (a3 + bias) * bscale + wo * tv.y;
        *(float4*)(op + y * Hn + x0) = o4;
    }
}

extern "C" void kernel_launch(void* const* d_in, const int* in_sizes, int n_in,
                              void* d_out, int out_size) {
    const float* x          = (const float*)d_in[0];
    const float* base_w     = (const float*)d_in[1];
    const float* base_b     = (const float*)d_in[2];
    const float* base_scale = (const float*)d_in[3];
    const float* wav_scale  = (const float*)d_in[4];
    const float* w_ll       = (const float*)d_in[5];
    const float* w_lh0      = (const float*)d_in[6];
    const float* w_hl0      = (const float*)d_in[7];
    const float* w_hh0      = (const float*)d_in[8];
    const float* w_lh1      = (const float*)d_in[9];
    const float* w_hl1      = (const float*)d_in[10];
    const float* w_hh1      = (const float*)d_in[11];
    float* out = (float*)d_out;

    k1_decompose<<<dim3(Bn * Cn, 14), dim3(56, 4)>>>(x);
    k2_s1<<<dim3(Bn * Cn, 7), dim3(56, 8)>>>(w_ll, w_lh1, w_hl1, w_hh1);
    k3_t0<<<dim3(Bn * Cn, 7), dim3(28, 8)>>>(w_lh0, w_hl0, w_hh0);
    k4_out<<<dim3(Bn * Cn, 14), dim3(56, 8)>>>(x, base_w, base_b, base_scale,
                                               wav_scale, out);
}

// round 5
// speedup vs baseline: 3.1984x; 1.4302x over previous
#include <cuda_runtime.h>

#define Bn 4
#define Cn 256
#define Hn 224
#define H0 112
#define H1 56

// Only t0 needs to round-trip through global now.
__device__ float g_t0[Bn*Cn*H0*H0];

// ---------------------------------------------------------------------------
// Kernel A: fused decompose(x) -> d0,d1 ; s1 = dw3x3(d1,Wsum1) ;
//           t0 = dw3x3(d0,Wsum0) + up(s1)*R_q.   One CTA per (b,c) plane.
// Smem: d0s[114][120] (zero halo, col offset 4), d1s[58][64] (halo, off 4),
//       s1s[56*56], ws1[9], ws0[9].  Total ~82.2KB dynamic.
// ---------------------------------------------------------------------------
#define D0S 13680   // 114*120
#define D1S 3712    // 58*64
#define S1S 3136    // 56*56

__global__ void kA(const float* __restrict__ x,
                   const float* __restrict__ wll, const float* __restrict__ wlh1,
                   const float* __restrict__ whl1, const float* __restrict__ whh1,
                   const float* __restrict__ wlh0, const float* __restrict__ whl0,
                   const float* __restrict__ whh0) {
    extern __shared__ float smem[];
    float* d0s = smem;               // [114][120]
    float* d1s = smem + D0S;         // [58][64]
    float* s1s = smem + D0S + D1S;   // [56*56]
    float* ws1 = smem + D0S + D1S + S1S;       // 9
    float* ws0 = smem + D0S + D1S + S1S + 16;  // 9

    int bc = blockIdx.x;
    int c  = bc & (Cn - 1);
    int tid = threadIdx.x;
    float sR = (c & 64)  ? -1.f : 1.f;
    float sC = (c & 128) ? -1.f : 1.f;

    // weights
    if (tid < 9) {
        int o = c * 9 + tid;
        ws1[tid] = wll[o] + wlh1[o] + whl1[o] + whh1[o];
    } else if (tid >= 32 && tid < 41) {
        int t = tid - 32;
        int o = c * 9 + t;
        ws0[t] = wlh0[o] + whl0[o] + whh0[o];
    }
    // zero halos
    for (int l = tid; l < 120; l += 512) { d0s[l] = 0.f; d0s[113*120 + l] = 0.f; }
    for (int l = tid; l < 114; l += 512) { d0s[l*120 + 3] = 0.f; d0s[l*120 + 116] = 0.f; }
    for (int l = tid; l < 64;  l += 512) { d1s[l] = 0.f; d1s[57*64 + l] = 0.f; }
    for (int l = tid; l < 58;  l += 512) { d1s[l*64 + 3] = 0.f; d1s[l*64 + 60] = 0.f; }

    // Phase 1: decompose x -> d0 (smem), d1 (smem). One d1 pixel per work item.
    const float* xp = x + (size_t)bc * Hn * Hn;
    for (int l = tid; l < 3136; l += 512) {
        int i = l / 56, j = l % 56;
        const float* p = xp + (4 * i) * Hn + 4 * j;
        float4 r0 = *(const float4*)(p);
        float4 r1 = *(const float4*)(p + Hn);
        float4 r2 = *(const float4*)(p + 2 * Hn);
        float4 r3 = *(const float4*)(p + 3 * Hn);
        float d00 = 0.25f * (r0.x + sC * r0.y + sR * (r1.x + sC * r1.y));
        float d01 = 0.25f * (r0.z + sC * r0.w + sR * (r1.z + sC * r1.w));
        float d10 = 0.25f * (r2.x + sC * r2.y + sR * (r3.x + sC * r3.y));
        float d11 = 0.25f * (r2.z + sC * r2.w + sR * (r3.z + sC * r3.w));
        float* q0 = d0s + (2 * i + 1) * 120 + 4 + 2 * j;
        q0[0] = d00; q0[1] = d01;
        q0[120] = d10; q0[121] = d11;
        d1s[(i + 1) * 64 + 4 + j] = 0.25f * (d00 + sC * d01 + sR * (d10 + sC * d11));
    }
    __syncthreads();

    // Phase 2: s1 = dw3x3(d1, ws1), zero pad.
    for (int l = tid; l < 3136; l += 512) {
        int u = l / 56, v = l % 56;
        float acc = 0.f;
        #pragma unroll
        for (int dy = 0; dy < 3; dy++) {
            const float* row = d1s + (u + dy) * 64 + 3 + v;
            acc += ws1[dy*3]   * row[0];
            acc += ws1[dy*3+1] * row[1];
            acc += ws1[dy*3+2] * row[2];
        }
        s1s[l] = acc;
    }
    __syncthreads();

    // Phase 3: t0 = dw3x3(d0, ws0) + up(s1)*R_q, write float4 to global.
    float svb = (c & 128) ? -1.f : 1.f;
    float* tp = g_t0 + (size_t)bc * H0 * H0;
    for (int l = tid; l < 3136; l += 512) {
        int y = l / 28, q = l % 28;
        int x0 = 4 * q;
        float a0 = 0.f, a1 = 0.f, a2 = 0.f, a3 = 0.f;
        #pragma unroll
        for (int dy = 0; dy < 3; dy++) {
            const float4* row4 = (const float4*)(d0s + (y + dy) * 120);
            float4 lq = row4[q], mq = row4[q + 1], rq = row4[q + 2];
            float w0 = ws0[dy*3], w1 = ws0[dy*3+1], w2 = ws0[dy*3+2];
            a0 += w0 * lq.w + w1 * mq.x + w2 * mq.y;
            a1 += w0 * mq.x + w1 * mq.y + w2 * mq.z;
            a2 += w0 * mq.y + w1 * mq.z + w2 * mq.w;
            a3 += w0 * mq.z + w1 * mq.w + w2 * rq.x;
        }
        float su = ((y & 1) && (c & 64)) ? -1.f : 1.f;
        float2 tv = *(const float2*)(s1s + (y >> 1) * H1 + 2 * q);
        float we = 0.5f * su, wo = 0.5f * su * svb;
        float4 o4;
        o4.x = a0 + we * tv.x;
        o4.y = a1 + wo * tv.x;
        o4.z = a2 + we * tv.y;
        o4.w = a3 + wo * tv.y;
        *(float4*)(tp + y * H0 + x0) = o4;
    }
}

// ---------------------------------------------------------------------------
// Kernel B: out = (dw3x3(x, base_w) + b)*bs + ws * up(t0)*R_q.
// Block (56,8): each thread computes a 4x4 output patch (224 cols x 32 rows
// per block). Conflict-free float4 LDS windows, 4-row register blocking.
// ---------------------------------------------------------------------------
__global__ void kB(const float* __restrict__ x, const float* __restrict__ bw,
                   const float* __restrict__ bb, const float* __restrict__ bs,
                   const float* __restrict__ ws, float* __restrict__ out) {
    __shared__ float w[9];
    __shared__ float sc[3];
    __shared__ float sm[34][232];   // col idx 4+x, zero pads idx 0..3, 228..231
    int bc = blockIdx.x;
    int c  = bc & (Cn - 1);
    int tx = threadIdx.x, ty = threadIdx.y;
    int tid = ty * 56 + tx;
    if (tid < 9)        w[tid] = bw[c * 9 + tid];
    else if (tid == 9)  sc[0] = bb[c];
    else if (tid == 10) sc[1] = bs[c];
    else if (tid == 11) sc[2] = ws[c];

    const float* xp = x + (size_t)bc * Hn * Hn;
    int Y0 = blockIdx.y * 32;
    // load 34 rows x 56 float4 (rows Y0-1 .. Y0+32), zero OOB
    for (int l = tid; l < 34 * 56; l += 448) {
        int r = l / 56, q = l % 56;
        int y = Y0 - 1 + r;
        float4 v4 = make_float4(0.f, 0.f, 0.f, 0.f);
        if (y >= 0 && y < Hn) v4 = *(const float4*)(xp + y * Hn + 4 * q);
        ((float4*)sm[r])[q + 1] = v4;
    }
    // zero side pads
    for (int l = tid; l < 34; l += 448) {
        ((float4*)sm[l])[0]  = make_float4(0.f, 0.f, 0.f, 0.f);
        ((float4*)sm[l])[57] = make_float4(0.f, 0.f, 0.f, 0.f);
    }
    __syncthreads();

    float a[4][4];
    #pragma unroll
    for (int j = 0; j < 4; j++) { a[j][0]=0.f; a[j][1]=0.f; a[j][2]=0.f; a[j][3]=0.f; }

    int r0 = 4 * ty;
    #pragma unroll
    for (int k = 0; k < 6; k++) {
        const float4* row4 = (const float4*)sm[r0 + k];
        float4 lq = row4[tx], mq = row4[tx + 1], rq = row4[tx + 2];
        float win0 = lq.w, win1 = mq.x, win2 = mq.y,
              win3 = mq.z, win4 = mq.w, win5 = rq.x;
        #pragma unroll
        for (int j = 0; j < 4; j++) {
            int wr = k - j;
            if (wr < 0 || wr > 2) continue;
            float w0 = w[wr*3], w1 = w[wr*3+1], w2 = w[wr*3+2];
            a[j][0] += w0 * win0 + w1 * win1 + w2 * win2;
            a[j][1] += w0 * win1 + w1 * win2 + w2 * win3;
            a[j][2] += w0 * win2 + w1 * win3 + w2 * win4;
            a[j][3] += w0 * win3 + w1 * win4 + w2 * win5;
        }
    }

    const float* tp = g_t0 + (size_t)bc * H0 * H0;
    float* op = out + (size_t)bc * Hn * Hn;
    int x0 = 4 * tx;
    int Y = Y0 + 4 * ty;                 // multiple of 4
    float svb = (c & 128) ? -1.f : 1.f;
    float bias = sc[0], bscale = sc[1], wsc = sc[2];
    float suo = (c & 64) ? -1.f : 1.f;   // sign on odd rows
    int tr = Y >> 1;
    float2 tva = *(const float2*)(tp + tr * H0 + 2 * tx);
    float2 tvb = *(const float2*)(tp + (tr + 1) * H0 + 2 * tx);
    #pragma unroll
    for (int j = 0; j < 4; j++) {
        float2 tv = (j < 2) ? tva : tvb;
        float su = (j & 1) ? suo : 1.f;
        float we = wsc * 0.5f * su, wo = we * svb;
        float4 o4;
        o4.x = (a[j][0] + bias) * bscale + we * tv.x;
        o4.y = (a[j][1] + bias) * bscale + wo * tv.x;
        o4.z = (a[j][2] + bias) * bscale + we * tv.y;
        o4.w = (a[j][3] + bias) * bscale + wo * tv.y;
        *(float4*)(op + (Y + j) * Hn + x0) = o4;
    }
}

extern "C" void kernel_launch(void* const* d_in, const int* in_sizes, int n_in,
                              void* d_out, int out_size) {
    const float* x          = (const float*)d_in[0];
    const float* base_w     = (const float*)d_in[1];
    const float* base_b     = (const float*)d_in[2];
    const float* base_scale = (const float*)d_in[3];
    const float* wav_scale  = (const float*)d_in[4];
    const float* w_ll       = (const float*)d_in[5];
    const float* w_lh0      = (const float*)d_in[6];
    const float* w_hl0      = (const float*)d_in[7];
    const float* w_hh0      = (const float*)d_in[8];
    const float* w_lh1      = (const float*)d_in[9];
    const float* w_hl1      = (const float*)d_in[10];
    const float* w_hh1      = (const float*)d_in[11];
    float* out = (float*)d_out;

    const int smemA = (D0S + D1S + S1S + 32) * sizeof(float);  // ~82.3KB
    // Unconditional (idempotent, deterministic) — no static guards allowed.
    cudaFuncSetAttribute(kA, cudaFuncAttributeMaxDynamicSharedMemorySize, smemA);
    kA<<<Bn * Cn, 512, smemA>>>(x, w_ll, w_lh1, w_hl1, w_hh1, w_lh0, w_hl0, w_hh0);
    kB<<<dim3(Bn * Cn, 7), dim3(56, 8)>>>(x, base_w, base_b, base_scale,
                                          wav_scale, out);
}

// round 6
// speedup vs baseline: 4.0350x; 1.2615x over previous
#include <cuda_runtime.h>

#define Bn 4
#define Cn 256
#define Hn 224

// smem layout (floats). Band = 56 output rows. All intermediates in smem.
#define XS_STRIDE 232   // x tile: 64 rows, col idx 4+xc, zero pads both sides
#define D0_STRIDE 120   // d0 tile: 30 rows, col idx 4+u, halo cols 3/116
#define D1_STRIDE 64    // d1 tile: 16 rows, col idx 4+v, halo cols 3/60
#define S1_STRIDE 56    // s1 tile: 14 rows
#define T0_STRIDE 116   // t0 tile: 28 rows

#define XS_OFF 0
#define D0_OFF (64*XS_STRIDE)                 // 14848
#define D1_OFF (D0_OFF + 30*D0_STRIDE)        // 18448
#define S1_OFF (D1_OFF + 16*D1_STRIDE)        // 19472
#define T0_OFF (S1_OFF + 14*S1_STRIDE)        // 20256
#define W_OFF  (T0_OFF + 28*T0_STRIDE)        // 23504
#define SMEM_FLOATS (W_OFF + 32)              // 23536 floats = 94144 B

__global__ void __launch_bounds__(512, 2)
kfused(const float* __restrict__ x,
       const float* __restrict__ bw,  const float* __restrict__ bb,
       const float* __restrict__ bs,  const float* __restrict__ wsv,
       const float* __restrict__ wll, const float* __restrict__ wlh1,
       const float* __restrict__ whl1,const float* __restrict__ whh1,
       const float* __restrict__ wlh0,const float* __restrict__ whl0,
       const float* __restrict__ whh0,
       float* __restrict__ out)
{
    extern __shared__ float smem[];
    float* xs  = smem + XS_OFF;
    float* d0s = smem + D0_OFF;
    float* d1s = smem + D1_OFF;
    float* s1s = smem + S1_OFF;
    float* t0s = smem + T0_OFF;
    float* wsh = smem + W_OFF;   // [0..8] ws1, [9..17] ws0, [18..26] base w, 27 b, 28 bs, 29 ws

    int bx = blockIdx.x;
    int bc = bx >> 2;            // (batch,channel) plane
    int B  = bx & 3;             // band: out rows [56B, 56B+56)
    int c  = bc & (Cn - 1);
    int tid = threadIdx.x;
    float sR = (c & 64)  ? -1.f : 1.f;
    float sC = (c & 128) ? -1.f : 1.f;

    if (tid < 9) {
        int o = c * 9 + tid;
        wsh[tid]      = wll[o] + wlh1[o] + whl1[o] + whh1[o];
        wsh[9 + tid]  = wlh0[o] + whl0[o] + whh0[o];
        wsh[18 + tid] = bw[o];
    } else if (tid == 9)  wsh[27] = bb[c];
    else if (tid == 10)   wsh[28] = bs[c];
    else if (tid == 11)   wsh[29] = wsv[c];
    // zero col halos for d0s / d1s
    if (tid >= 32 && tid < 62) {
        int r = tid - 32;
        d0s[r * D0_STRIDE + 3]   = 0.f;
        d0s[r * D0_STRIDE + 116] = 0.f;
    } else if (tid >= 64 && tid < 80) {
        int r = tid - 64;
        d1s[r * D1_STRIDE + 3]  = 0.f;
        d1s[r * D1_STRIDE + 60] = 0.f;
    }

    // ---- P1: stage x band: rows X0..X0+63 (zero OOB), cols padded by 4 ----
    int X0 = 56 * B - 4;
    const float* xp = x + (size_t)bc * Hn * Hn;
    #pragma unroll 4
    for (int l = tid; l < 64 * 58; l += 512) {
        int r = l / 58, f = l % 58;
        float4 v = make_float4(0.f, 0.f, 0.f, 0.f);
        int y = X0 + r;
        if (f >= 1 && f <= 56 && y >= 0 && y < Hn)
            v = *(const float4*)(xp + (size_t)y * Hn + 4 * (f - 1));
        ((float4*)(xs + r * XS_STRIDE))[f] = v;
    }
    __syncthreads();

    // ---- P2: decompose -> d0s (rows = d0 row (28B-1)+m), d1s (rows = d1 row (14B-1)+wl)
    for (int l = tid; l < 16 * 56; l += 512) {
        int wl = l / 56, j = l % 56;
        const float* p0 = xs + (4 * wl) * XS_STRIDE + 4 + 4 * j;
        float4 r0 = *(const float4*)(p0);
        float4 r1 = *(const float4*)(p0 + XS_STRIDE);
        float4 r2 = *(const float4*)(p0 + 2 * XS_STRIDE);
        float4 r3 = *(const float4*)(p0 + 3 * XS_STRIDE);
        float d00 = 0.25f * (r0.x + sC * r0.y + sR * (r1.x + sC * r1.y));
        float d01 = 0.25f * (r0.z + sC * r0.w + sR * (r1.z + sC * r1.w));
        float d10 = 0.25f * (r2.x + sC * r2.y + sR * (r3.x + sC * r3.y));
        float d11 = 0.25f * (r2.z + sC * r2.w + sR * (r3.z + sC * r3.w));
        int m0 = 2 * wl - 1;                     // d0 row of (d00,d01)
        if (m0 >= 0) {
            float* q = d0s + m0 * D0_STRIDE + 4 + 2 * j;
            q[0] = d00; q[1] = d01;
        }
        if (m0 + 1 < 30) {
            float* q = d0s + (m0 + 1) * D0_STRIDE + 4 + 2 * j;
            q[0] = d10; q[1] = d11;
        }
        d1s[wl * D1_STRIDE + 4 + j] =
            0.25f * (d00 + sC * d01 + sR * (d10 + sC * d11));
    }
    __syncthreads();

    // ---- P3: s1 = dw3x3(d1, ws1): rows m = s1 row 14B+m ----
    for (int l = tid; l < 14 * 56; l += 512) {
        int m = l / 56, v = l % 56;
        const float* base_ = d1s + m * D1_STRIDE + 3 + v;
        float acc = 0.f;
        #pragma unroll
        for (int dy = 0; dy < 3; dy++) {
            const float* row = base_ + dy * D1_STRIDE;
            acc += wsh[dy*3] * row[0] + wsh[dy*3+1] * row[1] + wsh[dy*3+2] * row[2];
        }
        s1s[m * S1_STRIDE + v] = acc;
    }
    __syncthreads();

    // ---- P4: t0 = dw3x3(d0, ws0) + up(s1)*R_q: rows m = t0 row 28B+m ----
    float svb = (c & 128) ? -1.f : 1.f;
    for (int l = tid; l < 28 * 28; l += 512) {
        int m = l / 28, q = l % 28;
        float a0 = 0.f, a1 = 0.f, a2 = 0.f, a3 = 0.f;
        #pragma unroll
        for (int dy = 0; dy < 3; dy++) {
            const float4* row4 = (const float4*)(d0s + (m + dy) * D0_STRIDE);
            float4 lq = row4[q], mq = row4[q + 1], rq = row4[q + 2];
            float w0 = wsh[9 + dy*3], w1 = wsh[9 + dy*3 + 1], w2 = wsh[9 + dy*3 + 2];
            a0 += w0 * lq.w + w1 * mq.x + w2 * mq.y;
            a1 += w0 * mq.x + w1 * mq.y + w2 * mq.z;
            a2 += w0 * mq.y + w1 * mq.z + w2 * mq.w;
            a3 += w0 * mq.z + w1 * mq.w + w2 * rq.x;
        }
        float su = ((m & 1) && (c & 64)) ? -1.f : 1.f;
        float2 tv = *(const float2*)(s1s + (m >> 1) * S1_STRIDE + 2 * q);
        float we = 0.5f * su, wo = we * svb;
        *(float4*)(t0s + m * T0_STRIDE + 4 * q) =
            make_float4(a0 + we * tv.x, a1 + wo * tv.x,
                        a2 + we * tv.y, a3 + wo * tv.y);
    }
    __syncthreads();

    // ---- P5: out rows 56B+n: 4x4 patches, xs rows n+3..n+5 per out row ----
    float bias = wsh[27], bscale = wsh[28], wsc = wsh[29];
    float suo = (c & 64) ? -1.f : 1.f;
    float* op = out + (size_t)bc * Hn * Hn;
    for (int l = tid; l < 14 * 56; l += 512) {
        int n0 = 4 * (l / 56), q = l % 56;
        float a[4][4];
        #pragma unroll
        for (int j = 0; j < 4; j++) { a[j][0]=0.f; a[j][1]=0.f; a[j][2]=0.f; a[j][3]=0.f; }
        #pragma unroll
        for (int k = 0; k < 6; k++) {
            const float4* row4 = (const float4*)(xs + (n0 + 3 + k) * XS_STRIDE);
            float4 lq = row4[q], mq = row4[q + 1], rq = row4[q + 2];
            float win0 = lq.w, win1 = mq.x, win2 = mq.y,
                  win3 = mq.z, win4 = mq.w, win5 = rq.x;
            #pragma unroll
            for (int j = 0; j < 4; j++) {
                int wr = k - j;
                if (wr < 0 || wr > 2) continue;
                float w0 = wsh[18 + wr*3], w1 = wsh[18 + wr*3 + 1], w2 = wsh[18 + wr*3 + 2];
                a[j][0] += w0 * win0 + w1 * win1 + w2 * win2;
                a[j][1] += w0 * win1 + w1 * win2 + w2 * win3;
                a[j][2] += w0 * win2 + w1 * win3 + w2 * win4;
                a[j][3] += w0 * win3 + w1 * win4 + w2 * win5;
            }
        }
        int tr = n0 >> 1;
        float2 tva = *(const float2*)(t0s + tr * T0_STRIDE + 2 * q);
        float2 tvb = *(const float2*)(t0s + (tr + 1) * T0_STRIDE + 2 * q);
        #pragma unroll
        for (int j = 0; j < 4; j++) {
            float2 tv = (j < 2) ? tva : tvb;
            float su = (j & 1) ? suo : 1.f;
            float we = wsc * 0.5f * su, wo = we * svb;
            float4 o4;
            o4.x = (a[j][0] + bias) * bscale + we * tv.x;
            o4.y = (a[j][1] + bias) * bscale + wo * tv.x;
            o4.z = (a[j][2] + bias) * bscale + we * tv.y;
            o4.w = (a[j][3] + bias) * bscale + wo * tv.y;
            *(float4*)(op + (size_t)(56 * B + n0 + j) * Hn + 4 * q) = o4;
        }
    }
}

extern "C" void kernel_launch(void* const* d_in, const int* in_sizes, int n_in,
                              void* d_out, int out_size) {
    const float* x          = (const float*)d_in[0];
    const float* base_w     = (const float*)d_in[1];
    const float* base_b     = (const float*)d_in[2];
    const float* base_scale = (const float*)d_in[3];
    const float* wav_scale  = (const float*)d_in[4];
    const float* w_ll       = (const float*)d_in[5];
    const float* w_lh0      = (const float*)d_in[6];
    const float* w_hl0      = (const float*)d_in[7];
    const float* w_hh0      = (const float*)d_in[8];
    const float* w_lh1      = (const float*)d_in[9];
    const float* w_hl1      = (const float*)d_in[10];
    const float* w_hh1      = (const float*)d_in[11];
    float* out = (float*)d_out;

    const int smemB = SMEM_FLOATS * sizeof(float);   // 94144 B
    cudaFuncSetAttribute(kfused, cudaFuncAttributeMaxDynamicSharedMemorySize, smemB);
    kfused<<<Bn * Cn * 4, 512, smemB>>>(x, base_w, base_b, base_scale, wav_scale,
                                        w_ll, w_lh1, w_hl1, w_hh1,
                                        w_lh0, w_hl0, w_hh0, out);
}

// round 7
// speedup vs baseline: 4.7175x; 1.1692x over previous
#include <cuda_runtime.h>

#define Bn 4
#define Cn 256
#define Hn 224

// smem strides (floats); all tiles band-local (band = 56 output rows)
#define D0_STRIDE 120   // 30 rows, data at col 4+u, zero halo cols 3 / 116
#define D1_STRIDE 64    // 16 rows, data at col 4+v, zero halo cols 3 / 60
#define S1_STRIDE 56    // 14 rows
#define T0_STRIDE 116   // 28 rows

__global__ void __launch_bounds__(512, 2)
kfused(const float* __restrict__ x,
       const float* __restrict__ bw,  const float* __restrict__ bb,
       const float* __restrict__ bs,  const float* __restrict__ wsv,
       const float* __restrict__ wll, const float* __restrict__ wlh1,
       const float* __restrict__ whl1,const float* __restrict__ whh1,
       const float* __restrict__ wlh0,const float* __restrict__ whl0,
       const float* __restrict__ whh0,
       float* __restrict__ out)
{
    __shared__ float d0s[30 * D0_STRIDE];
    __shared__ float d1s[16 * D1_STRIDE];
    __shared__ float s1s[14 * S1_STRIDE];
    __shared__ float t0s[28 * T0_STRIDE];
    __shared__ float wsh[32];  // [0..8] ws1, [9..17] ws0, [18..26] base, 27 b, 28 bs, 29 ws

    int bx = blockIdx.x;
    int bc = bx >> 2;            // (batch,channel) plane
    int B  = bx & 3;             // band: out rows [56B, 56B+56)
    int c  = bc & (Cn - 1);
    int tid = threadIdx.x;
    float sR = (c & 64)  ? -1.f : 1.f;
    float sC = (c & 128) ? -1.f : 1.f;

    if (tid < 9) {
        int o = c * 9 + tid;
        wsh[tid]      = wll[o] + wlh1[o] + whl1[o] + whh1[o];
        wsh[9 + tid]  = wlh0[o] + whl0[o] + whh0[o];
        wsh[18 + tid] = bw[o];
    } else if (tid == 9)  wsh[27] = bb[c];
    else if (tid == 10)   wsh[28] = bs[c];
    else if (tid == 11)   wsh[29] = wsv[c];
    // zero col halos
    if (tid >= 32 && tid < 62) {
        int r = tid - 32;
        d0s[r * D0_STRIDE + 3]   = 0.f;
        d0s[r * D0_STRIDE + 116] = 0.f;
    } else if (tid >= 64 && tid < 80) {
        int r = tid - 64;
        d1s[r * D1_STRIDE + 3]  = 0.f;
        d1s[r * D1_STRIDE + 60] = 0.f;
    }

    const float* xp = x + (size_t)bc * Hn * Hn;
    int X0 = 56 * B - 4;

    // ---- P1: decompose x -> d0s, d1s directly from global (896 items) ----
    for (int l = tid; l < 896; l += 512) {
        int wl = l / 56, j = l % 56;
        int y0 = X0 + 4 * wl;
        const float* p = xp + (size_t)y0 * Hn + 4 * j;
        float4 z4 = make_float4(0.f, 0.f, 0.f, 0.f);
        float4 r0 = (y0     >= 0 && y0     < Hn) ? *(const float4*)(p)          : z4;
        float4 r1 = (y0 + 1 >= 0 && y0 + 1 < Hn) ? *(const float4*)(p + Hn)     : z4;
        float4 r2 = (y0 + 2 >= 0 && y0 + 2 < Hn) ? *(const float4*)(p + 2 * Hn) : z4;
        float4 r3 = (y0 + 3 >= 0 && y0 + 3 < Hn) ? *(const float4*)(p + 3 * Hn) : z4;
        float d00 = 0.25f * (r0.x + sC * r0.y + sR * (r1.x + sC * r1.y));
        float d01 = 0.25f * (r0.z + sC * r0.w + sR * (r1.z + sC * r1.w));
        float d10 = 0.25f * (r2.x + sC * r2.y + sR * (r3.x + sC * r3.y));
        float d11 = 0.25f * (r2.z + sC * r2.w + sR * (r3.z + sC * r3.w));
        int m0 = 2 * wl - 1;
        if (m0 >= 0)     *(float2*)(d0s + m0 * D0_STRIDE + 4 + 2 * j) = make_float2(d00, d01);
        if (m0 + 1 < 30) *(float2*)(d0s + (m0 + 1) * D0_STRIDE + 4 + 2 * j) = make_float2(d10, d11);
        d1s[wl * D1_STRIDE + 4 + j] = 0.25f * (d00 + sC * d01 + sR * (d10 + sC * d11));
    }
    __syncthreads();

    // ---- P2: s1 = dw3x3(d1, ws1): 196 items (14 rows x 14 qcols) ----
    if (tid < 196) {
        int m = tid / 14, q = tid % 14;
        float a0 = 0.f, a1 = 0.f, a2 = 0.f, a3 = 0.f;
        #pragma unroll
        for (int dy = 0; dy < 3; dy++) {
            const float4* row4 = (const float4*)(d1s + (m + dy) * D1_STRIDE);
            float4 lq = row4[q], mq = row4[q + 1], rq = row4[q + 2];
            float w0 = wsh[dy*3], w1 = wsh[dy*3+1], w2 = wsh[dy*3+2];
            a0 += w0 * lq.w + w1 * mq.x + w2 * mq.y;
            a1 += w0 * mq.x + w1 * mq.y + w2 * mq.z;
            a2 += w0 * mq.y + w1 * mq.z + w2 * mq.w;
            a3 += w0 * mq.z + w1 * mq.w + w2 * rq.x;
        }
        *(float4*)(s1s + m * S1_STRIDE + 4 * q) = make_float4(a0, a1, a2, a3);
    }
    __syncthreads();

    // ---- P3: t0 = dw3x3(d0, ws0) + up(s1)*R_q: 392 items, 2 t0 rows each ----
    float svb = (c & 128) ? -1.f : 1.f;
    float suo = (c & 64)  ? -1.f : 1.f;
    if (tid < 392) {
        int mm = tid / 28, q = tid % 28;   // t0 rows 2mm, 2mm+1
        float rw[4][6];
        #pragma unroll
        for (int k = 0; k < 4; k++) {
            const float4* row4 = (const float4*)(d0s + (2 * mm + k) * D0_STRIDE);
            float4 lq = row4[q], mq = row4[q + 1], rq = row4[q + 2];
            rw[k][0] = lq.w; rw[k][1] = mq.x; rw[k][2] = mq.y;
            rw[k][3] = mq.z; rw[k][4] = mq.w; rw[k][5] = rq.x;
        }
        float2 sv = *(const float2*)(s1s + mm * S1_STRIDE + 2 * q);
        #pragma unroll
        for (int rr = 0; rr < 2; rr++) {
            float a0 = 0.f, a1 = 0.f, a2 = 0.f, a3 = 0.f;
            #pragma unroll
            for (int dy = 0; dy < 3; dy++) {
                const float* r = rw[rr + dy];
                float w0 = wsh[9 + dy*3], w1 = wsh[9 + dy*3 + 1], w2 = wsh[9 + dy*3 + 2];
                a0 += w0 * r[0] + w1 * r[1] + w2 * r[2];
                a1 += w0 * r[1] + w1 * r[2] + w2 * r[3];
                a2 += w0 * r[2] + w1 * r[3] + w2 * r[4];
                a3 += w0 * r[3] + w1 * r[4] + w2 * r[5];
            }
            float su = rr ? suo : 1.f;
            float we = 0.5f * su, wo = we * svb;
            *(float4*)(t0s + (2 * mm + rr) * T0_STRIDE + 4 * q) =
                make_float4(a0 + we * sv.x, a1 + wo * sv.x,
                            a2 + we * sv.y, a3 + wo * sv.y);
        }
    }
    __syncthreads();

    // ---- P4: out rows 56B..56B+55: 448 items, 7 rows x 4 cols each.
    //      x re-read via LDG (L1D-hot from P1). Sliding 3-row window. ----
    if (tid < 448) {
        int rg = tid / 56, q = tid % 56;   // band-local rows 7rg..7rg+6
        float wb[9];
        #pragma unroll
        for (int i = 0; i < 9; i++) wb[i] = wsh[18 + i];
        float bias = wsh[27], bscale = wsh[28], wsc = wsh[29];
        float* op = out + (size_t)bc * Hn * Hn;

        float win[3][6];
        int n0g = 56 * B + 7 * rg;         // global first output row
        // preload rows n0g-1, n0g
        #pragma unroll
        for (int pk = 0; pk < 2; pk++) {
            int y = n0g - 1 + pk;
            float* wrow = win[pk];
            if (y >= 0 && y < Hn) {
                const float* row = xp + (size_t)y * Hn;
                float4 v = *(const float4*)(row + 4 * q);
                wrow[0] = (q > 0)  ? row[4 * q - 1] : 0.f;
                wrow[1] = v.x; wrow[2] = v.y; wrow[3] = v.z; wrow[4] = v.w;
                wrow[5] = (q < 55) ? row[4 * q + 4] : 0.f;
            } else {
                wrow[0]=0.f; wrow[1]=0.f; wrow[2]=0.f; wrow[3]=0.f; wrow[4]=0.f; wrow[5]=0.f;
            }
        }
        #pragma unroll
        for (int i = 0; i < 7; i++) {
            // load row n0g+1+i into slot (i+2)%3
            {
                int y = n0g + 1 + i;
                float* wrow = win[(i + 2) % 3];
                if (y < Hn) {   // y >= 1 always here
                    const float* row = xp + (size_t)y * Hn;
                    float4 v = *(const float4*)(row + 4 * q);
                    wrow[0] = (q > 0)  ? row[4 * q - 1] : 0.f;
                    wrow[1] = v.x; wrow[2] = v.y; wrow[3] = v.z; wrow[4] = v.w;
                    wrow[5] = (q < 55) ? row[4 * q + 4] : 0.f;
                } else {
                    wrow[0]=0.f; wrow[1]=0.f; wrow[2]=0.f; wrow[3]=0.f; wrow[4]=0.f; wrow[5]=0.f;
                }
            }
            float a0 = 0.f, a1 = 0.f, a2 = 0.f, a3 = 0.f;
            #pragma unroll
            for (int dy = 0; dy < 3; dy++) {
                const float* r = win[(i + dy) % 3];
                float w0 = wb[dy*3], w1 = wb[dy*3+1], w2 = wb[dy*3+2];
                a0 += w0 * r[0] + w1 * r[1] + w2 * r[2];
                a1 += w0 * r[1] + w1 * r[2] + w2 * r[3];
                a2 += w0 * r[2] + w1 * r[3] + w2 * r[4];
                a3 += w0 * r[3] + w1 * r[4] + w2 * r[5];
            }
            int n = 7 * rg + i;            // band-local output row
            float2 tv = *(const float2*)(t0s + (n >> 1) * T0_STRIDE + 2 * q);
            float su = (n & 1) ? suo : 1.f;
            float we = wsc * 0.5f * su, wo = we * svb;
            float4 o4;
            o4.x = (a0 + bias) * bscale + we * tv.x;
            o4.y = (a1 + bias) * bscale + wo * tv.x;
            o4.z = (a2 + bias) * bscale + we * tv.y;
            o4.w = (a3 + bias) * bscale + wo * tv.y;
            *(float4*)(op + (size_t)(56 * B + n) * Hn + 4 * q) = o4;
        }
    }
}

extern "C" void kernel_launch(void* const* d_in, const int* in_sizes, int n_in,
                              void* d_out, int out_size) {
    const float* x          = (const float*)d_in[0];
    const float* base_w     = (const float*)d_in[1];
    const float* base_b     = (const float*)d_in[2];
    const float* base_scale = (const float*)d_in[3];
    const float* wav_scale  = (const float*)d_in[4];
    const float* w_ll       = (const float*)d_in[5];
    const float* w_lh0      = (const float*)d_in[6];
    const float* w_hl0      = (const float*)d_in[7];
    const float* w_hh0      = (const float*)d_in[8];
    const float* w_lh1      = (const float*)d_in[9];
    const float* w_hl1      = (const float*)d_in[10];
    const float* w_hh1      = (const float*)d_in[11];
    float* out = (float*)d_out;

    kfused<<<Bn * Cn * 4, 512>>>(x, base_w, base_b, base_scale, wav_scale,
                                 w_ll, w_lh1, w_hl1, w_hh1,
                                 w_lh0, w_hl0, w_hh0, out);
}

// round 8
// speedup vs baseline: 4.7288x; 1.0024x over previous
#include <cuda_runtime.h>

#define Bn 4
#define Cn 256
#define Hn 224

// smem strides (floats); all tiles band-local (band = 56 output rows)
#define D0_STRIDE 120   // 30 rows, data at col 4+u, zero halo cols 3 / 116
#define D1_STRIDE 64    // 16 rows, data at col 4+v, zero halo cols 3 / 60
#define S1_STRIDE 56    // 14 rows
#define T0_STRIDE 116   // 28 rows

// Load the 6-wide window (cols 4q-1 .. 4q+4) of x row y, using shuffles for
// the edge columns. All lanes of the warp with the same rg share y.
__device__ __forceinline__ void load_row_win(float* wrow, const float* __restrict__ xp,
                                             int y, int q, int lane) {
    float4 v = make_float4(0.f, 0.f, 0.f, 0.f);
    bool yv = (y >= 0) && (y < Hn);
    const float* row = xp + (size_t)y * Hn;
    if (yv) v = *(const float4*)(row + 4 * q);
    float lft = __shfl_up_sync(0xffffffffu, v.w, 1);
    float rgt = __shfl_down_sync(0xffffffffu, v.x, 1);
    if (lane == 0 && q > 0 && yv)   lft = row[4 * q - 1];
    if (lane == 31 && q < 55 && yv) rgt = row[4 * q + 4];
    if (q == 0)  lft = 0.f;
    if (q == 55) rgt = 0.f;
    wrow[0] = lft; wrow[1] = v.x; wrow[2] = v.y;
    wrow[3] = v.z; wrow[4] = v.w; wrow[5] = rgt;
}

__global__ void __launch_bounds__(512, 2)
kfused(const float* __restrict__ x,
       const float* __restrict__ bw,  const float* __restrict__ bb,
       const float* __restrict__ bs,  const float* __restrict__ wsv,
       const float* __restrict__ wll, const float* __restrict__ wlh1,
       const float* __restrict__ whl1,const float* __restrict__ whh1,
       const float* __restrict__ wlh0,const float* __restrict__ whl0,
       const float* __restrict__ whh0,
       float* __restrict__ out)
{
    __shared__ float d0s[30 * D0_STRIDE];
    __shared__ float d1s[16 * D1_STRIDE];
    __shared__ float s1s[14 * S1_STRIDE];
    __shared__ float t0s[28 * T0_STRIDE];
    __shared__ float wsh[32];  // [0..8] ws1, [9..17] ws0, [18..26] base, 27 b, 28 bs, 29 ws

    int bx = blockIdx.x;
    int bc = bx >> 2;            // (batch,channel) plane
    int B  = bx & 3;             // band: out rows [56B, 56B+56)
    int c  = bc & (Cn - 1);
    int tid = threadIdx.x;
    float sR = (c & 64)  ? -1.f : 1.f;
    float sC = (c & 128) ? -1.f : 1.f;

    if (tid < 9) {
        int o = c * 9 + tid;
        wsh[tid]      = wll[o] + wlh1[o] + whl1[o] + whh1[o];
        wsh[9 + tid]  = wlh0[o] + whl0[o] + whh0[o];
        wsh[18 + tid] = bw[o];
    } else if (tid == 9)  wsh[27] = bb[c];
    else if (tid == 10)   wsh[28] = bs[c];
    else if (tid == 11)   wsh[29] = wsv[c];
    // zero col halos
    if (tid >= 32 && tid < 62) {
        int r = tid - 32;
        d0s[r * D0_STRIDE + 3]   = 0.f;
        d0s[r * D0_STRIDE + 116] = 0.f;
    } else if (tid >= 64 && tid < 80) {
        int r = tid - 64;
        d1s[r * D1_STRIDE + 3]  = 0.f;
        d1s[r * D1_STRIDE + 60] = 0.f;
    }

    const float* xp = x + (size_t)bc * Hn * Hn;
    int X0 = 56 * B - 4;

    // ---- P1: decompose x -> d0s, d1s directly from global (896 items) ----
    for (int l = tid; l < 896; l += 512) {
        int wl = l / 56, j = l % 56;
        int y0 = X0 + 4 * wl;
        const float* p = xp + (size_t)y0 * Hn + 4 * j;
        float4 z4 = make_float4(0.f, 0.f, 0.f, 0.f);
        float4 r0 = (y0     >= 0 && y0     < Hn) ? *(const float4*)(p)          : z4;
        float4 r1 = (y0 + 1 >= 0 && y0 + 1 < Hn) ? *(const float4*)(p + Hn)     : z4;
        float4 r2 = (y0 + 2 >= 0 && y0 + 2 < Hn) ? *(const float4*)(p + 2 * Hn) : z4;
        float4 r3 = (y0 + 3 >= 0 && y0 + 3 < Hn) ? *(const float4*)(p + 3 * Hn) : z4;
        float d00 = 0.25f * (r0.x + sC * r0.y + sR * (r1.x + sC * r1.y));
        float d01 = 0.25f * (r0.z + sC * r0.w + sR * (r1.z + sC * r1.w));
        float d10 = 0.25f * (r2.x + sC * r2.y + sR * (r3.x + sC * r3.y));
        float d11 = 0.25f * (r2.z + sC * r2.w + sR * (r3.z + sC * r3.w));
        int m0 = 2 * wl - 1;
        if (m0 >= 0)     *(float2*)(d0s + m0 * D0_STRIDE + 4 + 2 * j) = make_float2(d00, d01);
        if (m0 + 1 < 30) *(float2*)(d0s + (m0 + 1) * D0_STRIDE + 4 + 2 * j) = make_float2(d10, d11);
        d1s[wl * D1_STRIDE + 4 + j] = 0.25f * (d00 + sC * d01 + sR * (d10 + sC * d11));
    }
    __syncthreads();

    // ---- P2: s1 = dw3x3(d1, ws1): 196 items (14 rows x 14 qcols) ----
    if (tid < 196) {
        int m = tid / 14, q = tid % 14;
        float a0 = 0.f, a1 = 0.f, a2 = 0.f, a3 = 0.f;
        #pragma unroll
        for (int dy = 0; dy < 3; dy++) {
            const float4* row4 = (const float4*)(d1s + (m + dy) * D1_STRIDE);
            float4 lq = row4[q], mq = row4[q + 1], rq = row4[q + 2];
            float w0 = wsh[dy*3], w1 = wsh[dy*3+1], w2 = wsh[dy*3+2];
            a0 += w0 * lq.w + w1 * mq.x + w2 * mq.y;
            a1 += w0 * mq.x + w1 * mq.y + w2 * mq.z;
            a2 += w0 * mq.y + w1 * mq.z + w2 * mq.w;
            a3 += w0 * mq.z + w1 * mq.w + w2 * rq.x;
        }
        *(float4*)(s1s + m * S1_STRIDE + 4 * q) = make_float4(a0, a1, a2, a3);
    }
    __syncthreads();

    // ---- P3: t0 = dw3x3(d0, ws0) + up(s1)*R_q: 392 items, 2 t0 rows each ----
    float svb = (c & 128) ? -1.f : 1.f;
    float suo = (c & 64)  ? -1.f : 1.f;
    if (tid < 392) {
        int mm = tid / 28, q = tid % 28;   // t0 rows 2mm, 2mm+1
        float rw[4][6];
        #pragma unroll
        for (int k = 0; k < 4; k++) {
            const float4* row4 = (const float4*)(d0s + (2 * mm + k) * D0_STRIDE);
            float4 lq = row4[q], mq = row4[q + 1], rq = row4[q + 2];
            rw[k][0] = lq.w; rw[k][1] = mq.x; rw[k][2] = mq.y;
            rw[k][3] = mq.z; rw[k][4] = mq.w; rw[k][5] = rq.x;
        }
        float2 sv = *(const float2*)(s1s + mm * S1_STRIDE + 2 * q);
        #pragma unroll
        for (int rr = 0; rr < 2; rr++) {
            float a0 = 0.f, a1 = 0.f, a2 = 0.f, a3 = 0.f;
            #pragma unroll
            for (int dy = 0; dy < 3; dy++) {
                const float* r = rw[rr + dy];
                float w0 = wsh[9 + dy*3], w1 = wsh[9 + dy*3 + 1], w2 = wsh[9 + dy*3 + 2];
                a0 += w0 * r[0] + w1 * r[1] + w2 * r[2];
                a1 += w0 * r[1] + w1 * r[2] + w2 * r[3];
                a2 += w0 * r[2] + w1 * r[3] + w2 * r[4];
                a3 += w0 * r[3] + w1 * r[4] + w2 * r[5];
            }
            float su = rr ? suo : 1.f;
            float we = 0.5f * su, wo = we * svb;
            *(float4*)(t0s + (2 * mm + rr) * T0_STRIDE + 4 * q) =
                make_float4(a0 + we * sv.x, a1 + wo * sv.x,
                            a2 + we * sv.y, a3 + wo * sv.y);
        }
    }
    __syncthreads();

    // ---- P4: out rows 56B..56B+55: 448 items (14 full warps), 7 rows x 4 cols.
    //      x re-read via LDG (L1D-hot from P1); edges via warp shuffle. ----
    if (tid < 448) {
        int rg = tid / 56, q = tid % 56;   // band-local rows 7rg..7rg+6
        int lane = tid & 31;
        float wb[9];
        #pragma unroll
        for (int i = 0; i < 9; i++) wb[i] = wsh[18 + i];
        float bias = wsh[27], bscale = wsh[28], wsc = wsh[29];
        float* op = out + (size_t)bc * Hn * Hn;

        float win[3][6];
        int n0g = 56 * B + 7 * rg;         // global first output row
        load_row_win(win[0], xp, n0g - 1, q, lane);
        load_row_win(win[1], xp, n0g,     q, lane);
        #pragma unroll
        for (int i = 0; i < 7; i++) {
            load_row_win(win[(i + 2) % 3], xp, n0g + 1 + i, q, lane);
            float a0 = 0.f, a1 = 0.f, a2 = 0.f, a3 = 0.f;
            #pragma unroll
            for (int dy = 0; dy < 3; dy++) {
                const float* r = win[(i + dy) % 3];
                float w0 = wb[dy*3], w1 = wb[dy*3+1], w2 = wb[dy*3+2];
                a0 += w0 * r[0] + w1 * r[1] + w2 * r[2];
                a1 += w0 * r[1] + w1 * r[2] + w2 * r[3];
                a2 += w0 * r[2] + w1 * r[3] + w2 * r[4];
                a3 += w0 * r[3] + w1 * r[4] + w2 * r[5];
            }
            int n = 7 * rg + i;            // band-local output row
            float2 tv = *(const float2*)(t0s + (n >> 1) * T0_STRIDE + 2 * q);
            float su = (n & 1) ? suo : 1.f;
            float we = wsc * 0.5f * su, wo = we * svb;
            float4 o4;
            o4.x = (a0 + bias) * bscale + we * tv.x;
            o4.y = (a1 + bias) * bscale + wo * tv.x;
            o4.z = (a2 + bias) * bscale + we * tv.y;
            o4.w = (a3 + bias) * bscale + wo * tv.y;
            *(float4*)(op + (size_t)(56 * B + n) * Hn + 4 * q) = o4;
        }
    }
}

extern "C" void kernel_launch(void* const* d_in, const int* in_sizes, int n_in,
                              void* d_out, int out_size) {
    const float* x          = (const float*)d_in[0];
    const float* base_w     = (const float*)d_in[1];
    const float* base_b     = (const float*)d_in[2];
    const float* base_scale = (const float*)d_in[3];
    const float* wav_scale  = (const float*)d_in[4];
    const float* w_ll       = (const float*)d_in[5];
    const float* w_lh0      = (const float*)d_in[6];
    const float* w_hl0      = (const float*)d_in[7];
    const float* w_hh0      = (const float*)d_in[8];
    const float* w_lh1      = (const float*)d_in[9];
    const float* w_hl1      = (const float*)d_in[10];
    const float* w_hh1      = (const float*)d_in[11];
    float* out = (float*)d_out;

    kfused<<<Bn * Cn * 4, 512>>>(x, base_w, base_b, base_scale, wav_scale,
                                 w_ll, w_lh1, w_hl1, w_hh1,
                                 w_lh0, w_hl0, w_hh0, out);
}

// round 10
// speedup vs baseline: 5.2413x; 1.1084x over previous
#include <cuda_runtime.h>

#define Bn 4
#define Cn 256
#define Hn 224

// Band = 28 output rows. All intermediates band-local in smem.
// d0s: 18 rows (global 14B-2 .. 14B+15), stride 120, data col 4+u, halos 3/116
// d1s:  9 rows (global 7B-1 .. 7B+7),   stride 64,  data col 4+v, halos 3/60
// s1s:  7 rows (global 7B .. 7B+6),     stride 56
// t0s: 14 rows (global 14B .. 14B+13),  stride 116
#define D0_STRIDE 120
#define D1_STRIDE 64
#define S1_STRIDE 56
#define T0_STRIDE 116

// 6-wide window (cols 4q-1..4q+4) of x row y; edge cols via warp shuffle.
__device__ __forceinline__ void load_row_win(float* wrow, const float* __restrict__ xp,
                                             int y, int q, int lane) {
    float4 v = make_float4(0.f, 0.f, 0.f, 0.f);
    bool yv = (y >= 0) && (y < Hn);
    const float* row = xp + (size_t)y * Hn;
    if (yv) v = *(const float4*)(row + 4 * q);
    float lft = __shfl_up_sync(0xffffffffu, v.w, 1);
    float rgt = __shfl_down_sync(0xffffffffu, v.x, 1);
    if (lane == 0 && q > 0 && yv)   lft = row[4 * q - 1];
    if (lane == 31 && q < 55 && yv) rgt = row[4 * q + 4];
    if (q == 0)  lft = 0.f;
    if (q == 55) rgt = 0.f;
    wrow[0] = lft; wrow[1] = v.x; wrow[2] = v.y;
    wrow[3] = v.z; wrow[4] = v.w; wrow[5] = rgt;
}

__global__ void __launch_bounds__(256, 4)
kfused(const float* __restrict__ x,
       const float* __restrict__ bw,  const float* __restrict__ bb,
       const float* __restrict__ bs,  const float* __restrict__ wsv,
       const float* __restrict__ wll, const float* __restrict__ wlh1,
       const float* __restrict__ whl1,const float* __restrict__ whh1,
       const float* __restrict__ wlh0,const float* __restrict__ whl0,
       const float* __restrict__ whh0,
       float* __restrict__ out)
{
    __shared__ float d0s[18 * D0_STRIDE];
    __shared__ float d1s[9 * D1_STRIDE];
    __shared__ float s1s[7 * S1_STRIDE];
    __shared__ float t0s[14 * T0_STRIDE];
    __shared__ float wsh[32];  // [0..8] ws1, [9..17] ws0, [18..26] base, 27 b, 28 bs, 29 ws

    int bx = blockIdx.x;
    int bc = bx >> 3;            // (batch,channel) plane
    int B  = bx & 7;             // band: out rows [28B, 28B+28)
    int c  = bc & (Cn - 1);
    int tid = threadIdx.x;
    float sR = (c & 64)  ? -1.f : 1.f;
    float sC = (c & 128) ? -1.f : 1.f;

    if (tid < 9) {
        int o = c * 9 + tid;
        wsh[tid]      = wll[o] + wlh1[o] + whl1[o] + whh1[o];
        wsh[9 + tid]  = wlh0[o] + whl0[o] + whh0[o];
        wsh[18 + tid] = bw[o];
    } else if (tid == 9)  wsh[27] = bb[c];
    else if (tid == 10)   wsh[28] = bs[c];
    else if (tid == 11)   wsh[29] = wsv[c];
    // zero col halos
    if (tid >= 32 && tid < 50) {
        int r = tid - 32;
        d0s[r * D0_STRIDE + 3]   = 0.f;
        d0s[r * D0_STRIDE + 116] = 0.f;
    } else if (tid >= 64 && tid < 73) {
        int r = tid - 64;
        d1s[r * D1_STRIDE + 3]  = 0.f;
        d1s[r * D1_STRIDE + 60] = 0.f;
    }

    const float* xp = x + (size_t)bc * Hn * Hn;
    int X0 = 28 * B - 4;   // x row of d0 local row 0 (pair start)

    // ---- P1: decompose x -> d0s (18 rows), d1s (9 rows); 504 items ----
    for (int l = tid; l < 504; l += 256) {
        int wl = l / 56, j = l % 56;          // wl = d1 local row 0..8
        int y0 = X0 + 4 * wl;
        const float* p = xp + (size_t)y0 * Hn + 4 * j;
        float4 z4 = make_float4(0.f, 0.f, 0.f, 0.f);
        float4 r0 = (y0     >= 0 && y0     < Hn) ? *(const float4*)(p)          : z4;
        float4 r1 = (y0 + 1 >= 0 && y0 + 1 < Hn) ? *(const float4*)(p + Hn)     : z4;
        float4 r2 = (y0 + 2 >= 0 && y0 + 2 < Hn) ? *(const float4*)(p + 2 * Hn) : z4;
        float4 r3 = (y0 + 3 >= 0 && y0 + 3 < Hn) ? *(const float4*)(p + 3 * Hn) : z4;
        float d00 = 0.25f * (r0.x + sC * r0.y + sR * (r1.x + sC * r1.y));
        float d01 = 0.25f * (r0.z + sC * r0.w + sR * (r1.z + sC * r1.w));
        float d10 = 0.25f * (r2.x + sC * r2.y + sR * (r3.x + sC * r3.y));
        float d11 = 0.25f * (r2.z + sC * r2.w + sR * (r3.z + sC * r3.w));
        int m0 = 2 * wl;                       // d0 local rows m0, m0+1 (0..17)
        *(float2*)(d0s + m0 * D0_STRIDE + 4 + 2 * j)       = make_float2(d00, d01);
        *(float2*)(d0s + (m0 + 1) * D0_STRIDE + 4 + 2 * j) = make_float2(d10, d11);
        d1s[wl * D1_STRIDE + 4 + j] = 0.25f * (d00 + sC * d01 + sR * (d10 + sC * d11));
    }
    __syncthreads();

    // ---- P2: s1 = dw3x3(d1, ws1): 98 items (7 rows x 14 qcols) ----
    if (tid < 98) {
        int m = tid / 14, q = tid % 14;
        float a0 = 0.f, a1 = 0.f, a2 = 0.f, a3 = 0.f;
        #pragma unroll
        for (int dy = 0; dy < 3; dy++) {
            const float4* row4 = (const float4*)(d1s + (m + dy) * D1_STRIDE);
            float4 lq = row4[q], mq = row4[q + 1], rq = row4[q + 2];
            float w0 = wsh[dy*3], w1 = wsh[dy*3+1], w2 = wsh[dy*3+2];
            a0 += w0 * lq.w + w1 * mq.x + w2 * mq.y;
            a1 += w0 * mq.x + w1 * mq.y + w2 * mq.z;
            a2 += w0 * mq.y + w1 * mq.z + w2 * mq.w;
            a3 += w0 * mq.z + w1 * mq.w + w2 * rq.x;
        }
        *(float4*)(s1s + m * S1_STRIDE + 4 * q) = make_float4(a0, a1, a2, a3);
    }
    __syncthreads();

    // ---- P3: t0 = dw3x3(d0, ws0) + up(s1)*R_q: 196 items, 2 t0 rows each ----
    float svb = (c & 128) ? -1.f : 1.f;
    float suo = (c & 64)  ? -1.f : 1.f;
    if (tid < 196) {
        int mm = tid / 28, q = tid % 28;   // t0 local rows 2mm, 2mm+1
        float rw[4][6];
        #pragma unroll
        for (int k = 0; k < 4; k++) {
            // d0 local rows 2mm+1 .. 2mm+4 (global (14B+2mm)-1 .. +2)
            const float4* row4 = (const float4*)(d0s + (2 * mm + 1 + k) * D0_STRIDE);
            float4 lq = row4[q], mq = row4[q + 1], rq = row4[q + 2];
            rw[k][0] = lq.w; rw[k][1] = mq.x; rw[k][2] = mq.y;
            rw[k][3] = mq.z; rw[k][4] = mq.w; rw[k][5] = rq.x;
        }
        float2 sv = *(const float2*)(s1s + mm * S1_STRIDE + 2 * q);
        #pragma unroll
        for (int rr = 0; rr < 2; rr++) {
            float a0 = 0.f, a1 = 0.f, a2 = 0.f, a3 = 0.f;
            #pragma unroll
            for (int dy = 0; dy < 3; dy++) {
                const float* r = rw[rr + dy];
                float w0 = wsh[9 + dy*3], w1 = wsh[9 + dy*3 + 1], w2 = wsh[9 + dy*3 + 2];
                a0 += w0 * r[0] + w1 * r[1] + w2 * r[2];
                a1 += w0 * r[1] + w1 * r[2] + w2 * r[3];
                a2 += w0 * r[2] + w1 * r[3] + w2 * r[4];
                a3 += w0 * r[3] + w1 * r[4] + w2 * r[5];
            }
            float su = rr ? suo : 1.f;       // parity of global t0 row = rr
            float we = 0.5f * su, wo = we * svb;
            *(float4*)(t0s + (2 * mm + rr) * T0_STRIDE + 4 * q) =
                make_float4(a0 + we * sv.x, a1 + wo * sv.x,
                            a2 + we * sv.y, a3 + wo * sv.y);
        }
    }
    __syncthreads();

    // ---- P4: out rows 28B..28B+27: 224 items (7 warps), 7 rows x 4 cols ----
    if (tid < 224) {
        int rg = tid / 56, q = tid % 56;   // band-local rows 7rg..7rg+6
        int lane = tid & 31;
        float wb[9];
        #pragma unroll
        for (int i = 0; i < 9; i++) wb[i] = wsh[18 + i];
        float bias = wsh[27], bscale = wsh[28], wsc = wsh[29];
        float* op = out + (size_t)bc * Hn * Hn;

        float win[3][6];
        int n0g = 28 * B + 7 * rg;         // global first output row
        load_row_win(win[0], xp, n0g - 1, q, lane);
        load_row_win(win[1], xp, n0g,     q, lane);
        #pragma unroll
        for (int i = 0; i < 7; i++) {
            load_row_win(win[(i + 2) % 3], xp, n0g + 1 + i, q, lane);
            float a0 = 0.f, a1 = 0.f, a2 = 0.f, a3 = 0.f;
            #pragma unroll
            for (int dy = 0; dy < 3; dy++) {
                const float* r = win[(i + dy) % 3];
                float w0 = wb[dy*3], w1 = wb[dy*3+1], w2 = wb[dy*3+2];
                a0 += w0 * r[0] + w1 * r[1] + w2 * r[2];
                a1 += w0 * r[1] + w1 * r[2] + w2 * r[3];
                a2 += w0 * r[2] + w1 * r[3] + w2 * r[4];
                a3 += w0 * r[3] + w1 * r[4] + w2 * r[5];
            }
            int n = 7 * rg + i;            // band-local output row
            float2 tv = *(const float2*)(t0s + (n >> 1) * T0_STRIDE + 2 * q);
            float su = (n & 1) ? suo : 1.f;
            float we = wsc * 0.5f * su, wo = we * svb;
            float4 o4;
            o4.x = (a0 + bias) * bscale + we * tv.x;
            o4.y = (a1 + bias) * bscale + wo * tv.x;
            o4.z = (a2 + bias) * bscale + we * tv.y;
            o4.w = (a3 + bias) * bscale + wo * tv.y;
            *(float4*)(op + (size_t)(28 * B + n) * Hn + 4 * q) = o4;
        }
    }
}

extern "C" void kernel_launch(void* const* d_in, const int* in_sizes, int n_in,
                              void* d_out, int out_size) {
    const float* x          = (const float*)d_in[0];
    const float* base_w     = (const float*)d_in[1];
    const float* base_b     = (const float*)d_in[2];
    const float* base_scale = (const float*)d_in[3];
    const float* wav_scale  = (const float*)d_in[4];
    const float* w_ll       = (const float*)d_in[5];
    const float* w_lh0      = (const float*)d_in[6];
    const float* w_hl0      = (const float*)d_in[7];
    const float* w_hh0      = (const float*)d_in[8];
    const float* w_lh1      = (const float*)d_in[9];
    const float* w_hl1      = (const float*)d_in[10];
    const float* w_hh1      = (const float*)d_in[11];
    float* out = (float*)d_out;

    kfused<<<Bn * Cn * 8, 256>>>(x, base_w, base_b, base_scale, wav_scale,
                                 w_ll, w_lh1, w_hl1, w_hh1,
                                 w_lh0, w_hl0, w_hh0, out);
}